// round 14
// baseline (speedup 1.0000x reference)
#include <cuda_runtime.h>
#include <cuda_fp16.h>
#include <cstdint>

// ---------------- problem constants ----------------
#define GGRP   8
#define DDISP  64
#define EDIM   128
#define K1DIM  72            // G*9
#define MTOT   409600        // N*NS
#define TILE_M 128           // 8 warps x m16
#define NTILES 3200          // MTOT / TILE_M
#define GRID_X 304           // 2 CTAs per SM
#define NTHR   256
#define EMB_ELEMS 52428800   // MTOT*EDIM
#define TOT_ELEMS 52838400   // + MTOT

// ---------------- smem layout (per CTA: 112768 B -> 2 CTAs/SM) ----------------
// A1: u32 words, row stride 44 (LDSM rows conflict-free, 176B 16B-aligned)
// B quad layout for LDS.128: quad idx = s*264 + ti*66 + jp*8 + g
// REC: per-warp 1-pixel staging: 8 groups x 68 floats = 2176 B
#define A1_STRIDE 44
#define BQ_S     264
#define NSTEP2   12                               // 8 real + 4 one-hot
#define REC_G    68
#define REC_WARP_BYTES (GGRP*REC_G*4)             // 2176

#define OFF_BIAS1 0                               // 512
#define OFF_BIAS2 512                             // 512 (prologue temp)
#define OFF_B1    1024                            // 5*264*16 = 21120
#define OFF_B2    (OFF_B1 + 5*BQ_S*16)            // 12*264*16 = 50688
#define OFF_A1    (OFF_B2 + NSTEP2*BQ_S*16)       // 128*44*4 = 22528
#define OFF_REC   (OFF_A1 + TILE_M*A1_STRIDE*4)   // 8*2176 = 17408
#define SMEM_TOTAL (OFF_REC + 8*REC_WARP_BYTES)   // 112768 B

// prologue: WpT f16 staging at OFF_A1, spans A1+REC free union (33792 <= 39936)
#define WPT_STRIDE 66

// ---------------- helpers ----------------
__device__ __forceinline__ void mma_f16(float c[4], uint32_t a0, uint32_t a1,
                                        uint32_t a2, uint32_t a3,
                                        uint32_t b0, uint32_t b1) {
    asm volatile(
        "mma.sync.aligned.m16n8k16.row.col.f32.f16.f16.f32 "
        "{%0,%1,%2,%3}, {%4,%5,%6,%7}, {%8,%9}, {%0,%1,%2,%3};"
        : "+f"(c[0]), "+f"(c[1]), "+f"(c[2]), "+f"(c[3])
        : "r"(a0), "r"(a1), "r"(a2), "r"(a3), "r"(b0), "r"(b1));
}

__device__ __forceinline__ void ldsm_x4(uint32_t a[4], uint32_t addr) {
    asm volatile("ldmatrix.sync.aligned.m8n8.x4.shared.b16 {%0,%1,%2,%3}, [%4];"
        : "=r"(a[0]), "=r"(a[1]), "=r"(a[2]), "=r"(a[3]) : "r"(addr));
}

__device__ __forceinline__ float gelu_fast(float x) {
    float p = x * fmaf(x * x, 0.0713548163f, 1.5957691216f);
    float e;
    asm("ex2.approx.ftz.f32 %0, %1;" : "=f"(e) : "f"(-1.4426950408889634f * p));
    float r;
    asm("rcp.approx.ftz.f32 %0, %1;" : "=f"(r) : "f"(1.0f + e));
    return x * r;
}

__device__ __forceinline__ uint32_t pack_h2(float lo, float hi) {
    __half2 h = __floats2half2_rn(lo, hi);
    return *(uint32_t*)&h;
}

__device__ __forceinline__ uint32_t oh2(int d, int kb) {
    uint32_t r = (d == kb) ? 0x3C00u : 0u;
    if (d == kb + 1) r |= 0x3C000000u;
    return r;
}

__device__ __forceinline__ uint32_t smem_u32(const void* p) {
    uint32_t a;
    asm("{ .reg .u64 t; cvta.to.shared.u64 t, %1; cvt.u32.u64 %0, t; }" : "=r"(a) : "l"(p));
    return a;
}

#define CP_ASYNC16(dst, src) \
    asm volatile("cp.async.cg.shared.global [%0], [%1], 16;" :: "r"(dst), "l"(src))
#define CP_COMMIT()  asm volatile("cp.async.commit_group;")
#define CP_WAIT0()   asm volatile("cp.async.wait_group 0;")

// half index in B QUAD layout for element (k, n)
__device__ __forceinline__ int b_half_idx(int k, int n) {
    int kp = k >> 1, h = k & 1;
    int s = kp >> 3, rem = kp & 7;
    int ti = rem & 3, w = rem >> 2;
    int g = n & 7, j = n >> 3, jp = j >> 1, jh = j & 1;
    int word = s * (BQ_S * 4) + ti * 264 + jp * 32 + g * 4 + jh * 2 + w;
    return word * 2 + h;
}

// ---- branchless 12->9 window select (validated) ----
struct GWin { int qb; bool o1, o2, neg, a1, a2, a4; };
__device__ __forceinline__ GWin gwin(int dcl) {
    int base = dcl - 4;
    int st = base < 0 ? 0 : (base > 55 ? 55 : base);
    int lo = base - st;
    GWin w;
    w.qb = st >> 2;
    int off = st & 3;
    w.o1 = off & 1;  w.o2 = off & 2;
    w.neg = lo < 0;
    int a = w.neg ? -lo : lo;
    w.a1 = a & 1;  w.a2 = a & 2;  w.a4 = a & 4;
    return w;
}

__device__ __forceinline__ void gselect(const GWin& w, const float4 c[3], float v[9]) {
    float f[12] = {c[0].x, c[0].y, c[0].z, c[0].w,
                   c[1].x, c[1].y, c[1].z, c[1].w,
                   c[2].x, c[2].y, c[2].z, c[2].w};
    float t[11], h[9];
    #pragma unroll
    for (int i = 0; i < 11; i++) t[i] = w.o1 ? f[i + 1] : f[i];
    #pragma unroll
    for (int i = 0; i < 9; i++)  h[i] = w.o2 ? t[i + 2] : t[i];
    #pragma unroll
    for (int i = 0; i < 9; i++) {
        float sh = w.neg ? h[i > 0 ? i - 1 : 0] : h[i < 8 ? i + 1 : 8];
        t[i] = w.a1 ? sh : h[i];
    }
    #pragma unroll
    for (int i = 0; i < 9; i++) {
        float sh = w.neg ? t[i > 1 ? i - 2 : 0] : t[i < 7 ? i + 2 : 8];
        h[i] = w.a2 ? sh : t[i];
    }
    #pragma unroll
    for (int i = 0; i < 9; i++) {
        float sh = w.neg ? h[i > 3 ? i - 4 : 0] : h[i < 5 ? i + 4 : 8];
        v[i] = w.a4 ? sh : h[i];
    }
}

// stage ONE pixel record (2 KB) densely via 4 cp.async per lane
__device__ __forceinline__ void stage_pixel(uint32_t rec_sa, const float* __restrict__ gsrc,
                                            int lid) {
    #pragma unroll
    for (int u = 0; u < 4; u++) {
        int gg = u * 2 + (lid >> 4);
        uint32_t dst = rec_sa + ((gg * REC_G + (lid & 15) * 4)) * 4;
        CP_ASYNC16(dst, gsrc + u * 128 + lid * 4);
    }
    CP_COMMIT();
}

// extract: lane = (seed s = lid>>3, group grp = lid&7); writes row 4p+s, k=9g..9g+8
__device__ __forceinline__ void extract_batch(const float* __restrict__ recw,
                                              __half* __restrict__ A1h,
                                              int p, int draw, int lid) {
    int s = lid >> 3, grp = lid & 7;
    int dcl = draw < 0 ? 0 : (draw > 63 ? 63 : draw);
    GWin w = gwin(dcl);
    const float4* s4 = (const float4*)(recw + grp * REC_G) + w.qb;
    float4 c[3] = {s4[0], s4[1], s4[2]};
    float v[9];
    gselect(w, c, v);
    __half* dst = A1h + (4 * p + s) * (A1_STRIDE * 2) + 9 * grp;
    #pragma unroll
    for (int i = 0; i < 9; i++) dst[i] = __float2half(v[i]);
}

// ---------------- single fused kernel ----------------
__global__ void __launch_bounds__(NTHR, 2)
propagation_kernel(const float* __restrict__ cost, const int* __restrict__ label,
                   const float* __restrict__ W1, const float* __restrict__ b1,
                   const float* __restrict__ W2, const float* __restrict__ b2,
                   const float* __restrict__ Wp,
                   float* __restrict__ out_embed, float* __restrict__ out_label) {
    extern __shared__ char smem[];
    const int tid = threadIdx.x;
    const int wid = tid >> 5, lid = tid & 31;
    const int g = lid >> 2, ti = lid & 3;
    const int mbase = wid * 16;               // warp owns rows [mbase, mbase+16)
    const int lrow = lid >> 3;                // extraction seed (0..3)

    float*    b1s   = (float*)(smem + OFF_BIAS1);
    float*    b2ps  = (float*)(smem + OFF_BIAS2);
    const uint4* B1q = (const uint4*)(smem + OFF_B1);
    const uint4* B2q = (const uint4*)(smem + OFF_B2);
    __half*   B1h   = (__half*)(smem + OFF_B1);
    __half*   B2h   = (__half*)(smem + OFF_B2);
    uint32_t* A1u   = (uint32_t*)(smem + OFF_A1);
    float*    recw  = (float*)(smem + OFF_REC + wid * REC_WARP_BYTES);
    const uint32_t rec_sa = smem_u32(recw);

    // ================= PROLOGUE =================
    // stage WpT (f16, [n][jp], stride 66 words) at OFF_A1 (spans free A1+REC union)
    {
        __half* WpTsh = (__half*)(smem + OFF_A1);
        for (int idx = tid; idx < EDIM * EDIM; idx += NTHR) {
            int jj = idx >> 7, n = idx & 127;
            WpTsh[(n * WPT_STRIDE + (jj >> 1)) * 2 + (jj & 1)] = __float2half(__ldg(Wp + idx));
        }
        for (int idx = tid; idx < K1DIM * EDIM; idx += NTHR) {
            int k = idx >> 7, n = idx & 127;
            B1h[b_half_idx(k, n)] = __float2half(__ldg(W1 + idx));
        }
        // zero B1 pad words (kp 36..39 -> s=4, w=1)
        for (int i = tid; i < 512; i += NTHR) {
            int t4 = i >> 7, rem = i & 127;
            int jp = rem >> 4, gg = (rem >> 1) & 7, jh = rem & 1;
            ((uint32_t*)(smem + OFF_B1))[4 * (BQ_S * 4) + t4 * 264 + jp * 32 + gg * 4 + jh * 2 + 1] = 0;
        }
        if (tid < EDIM) b1s[tid] = __ldg(b1 + tid);
    }
    __syncthreads();

    {   // fold W2p = W2 @ Wp_top : A-frags straight from gmem (round-8 pattern)
        const uint32_t* WpTs = (const uint32_t*)(smem + OFF_A1);
        const float* w2r0 = W2 + (size_t)(mbase + g) * EDIM;
        const float* w2r1 = W2 + (size_t)(mbase + g + 8) * EDIM;
        float facc[16][4];
        #pragma unroll
        for (int j = 0; j < 16; j++)
            #pragma unroll
            for (int u = 0; u < 4; u++) facc[j][u] = 0.f;
        #pragma unroll
        for (int s = 0; s < 8; s++) {
            int k0 = 16 * s + 2 * ti;
            float2 p0 = *(const float2*)(w2r0 + k0);
            float2 p1 = *(const float2*)(w2r1 + k0);
            float2 p2 = *(const float2*)(w2r0 + k0 + 8);
            float2 p3 = *(const float2*)(w2r1 + k0 + 8);
            uint32_t a0 = pack_h2(p0.x, p0.y), a1 = pack_h2(p1.x, p1.y);
            uint32_t a2 = pack_h2(p2.x, p2.y), a3 = pack_h2(p3.x, p3.y);
            int jp0 = 8 * s + ti;
            #pragma unroll
            for (int j = 0; j < 16; j++) {
                uint32_t b0 = WpTs[(8 * j + g) * WPT_STRIDE + jp0];
                uint32_t b1v = WpTs[(8 * j + g) * WPT_STRIDE + jp0 + 4];
                mma_f16(facc[j], a0, a1, a2, a3, b0, b1v);
            }
        }
        #pragma unroll
        for (int j = 0; j < 16; j++) {
            int n0 = 8 * j + 2 * ti;
            B2h[b_half_idx(mbase + g, n0)]     = __float2half(facc[j][0]);
            B2h[b_half_idx(mbase + g, n0 + 1)] = __float2half(facc[j][1]);
            B2h[b_half_idx(mbase + g + 8, n0)]     = __float2half(facc[j][2]);
            B2h[b_half_idx(mbase + g + 8, n0 + 1)] = __float2half(facc[j][3]);
        }
        if (tid < EDIM) {
            float ba = 0.f;
            #pragma unroll 8
            for (int j = 0; j < EDIM; j++) ba += __ldg(b2 + j) * __ldg(Wp + (size_t)j * EDIM + tid);
            b2ps[tid] = ba;
        }
    }
    __syncthreads();   // WpT staging dead

    {   // fourier scratch in A1 region (8 KB)
        float* scr = (float*)(smem + OFF_A1);
        for (int t = tid; t < 960; t += NTHR) {
            int d = t / 15, i = t - d * 15;
            float coordf = (float)d * (float)(3.14 / 64.0);
            float fr = coordf * (float)(1 << i);
            scr[d * 32 + i]      = (float)sin((double)fr);
            scr[d * 32 + 15 + i] = (float)cos((double)fr);
            if (i == 0) scr[d * 32 + 30] = coordf;
        }
    }
    __syncthreads();

    {   // table rows -> B2 steps 8..11
        const float* scr = (const float*)(smem + OFF_A1);
        int n = tid & 127, dh = tid >> 7;
        float wpc[31];
        #pragma unroll
        for (int c = 0; c < 31; c++) wpc[c] = __ldg(Wp + (size_t)(EDIM + c) * EDIM + n);
        float bb = b2ps[n];
        #pragma unroll 4
        for (int u = 0; u < 32; u++) {
            int d = dh + 2 * u;
            float acc = bb;
            #pragma unroll
            for (int c = 0; c < 31; c++) acc += scr[d * 32 + c] * wpc[c];
            B2h[b_half_idx(128 + d, n)] = __float2half(acc);
        }
    }
    __syncthreads();   // scratch dead; A1 region live from here

    // zero A1 K-pad words (kp 36..39) for this warp's 16 rows
    uint32_t* A1w = A1u + mbase * A1_STRIDE;
    __half*   A1h = (__half*)A1w;
    for (int i = lid; i < 64; i += 32)
        A1w[(i >> 2) * A1_STRIDE + 36 + (i & 3)] = 0;

    // ldmatrix lane address
    const uint32_t a1_sa = smem_u32(A1w);
    const uint32_t a_base = a1_sa + (((lid & 15) * A1_STRIDE + (lid >> 4) * 4) << 2);

    // first tile: stage + extract 4 pixel batches
    {
        int t0 = blockIdx.x;
        #pragma unroll
        for (int p = 0; p < 4; p++) {
            int pix = t0 * 32 + wid * 4 + p;
            stage_pixel(rec_sa, cost + (size_t)pix * (GGRP * DDISP), lid);
            int draw = __ldg(label + t0 * TILE_M + mbase + 4 * p + lrow);
            CP_WAIT0();
            __syncwarp();
            extract_batch(recw, A1h, p, draw, lid);
            if ((lid & 7) == 0 && out_label)
                out_label[t0 * TILE_M + mbase + 4 * p + lrow] = (float)draw;
            __syncwarp();
        }
    }

    // ================= MAIN LOOP =================
    for (int tile = blockIdx.x; tile < NTILES; tile += GRID_X) {
        const int m0 = tile * TILE_M;
        const int nxt = tile + GRID_X;
        const bool hn = nxt < NTILES;

        // one-hot labels for this tile's epilogue rows (broadcast sectors, L2-hit)
        int d0 = __ldg(label + m0 + mbase + g);
        int d1 = __ldg(label + m0 + mbase + g + 8);
        d0 = d0 < 0 ? 0 : (d0 > 63 ? 63 : d0);
        d1 = d1 < 0 ? 0 : (d1 > 63 ? 63 : d1);

        // next-tile labels for extraction (per batch)
        int drawn[4];
        if (hn) {
            #pragma unroll
            for (int p = 0; p < 4; p++)
                drawn[p] = __ldg(label + nxt * TILE_M + mbase + 4 * p + lrow);
        }

        // ---- GEMM1 (two n-halves) -> ha[8][4] ----
        uint32_t ha[8][4];
        #pragma unroll
        for (int hf = 0; hf < 2; hf++) {
            float acc1[8][4];
            #pragma unroll
            for (int j = 0; j < 8; j++)
                #pragma unroll
                for (int u = 0; u < 4; u++) acc1[j][u] = 0.f;
            #pragma unroll
            for (int s = 0; s < 5; s++) {
                uint32_t a[4];
                ldsm_x4(a, a_base + s * 32);
                const uint4* bq = B1q + s * BQ_S + ti * 66 + (4 * hf) * 8 + g;
                #pragma unroll
                for (int jp = 0; jp < 4; jp++) {
                    uint4 b = bq[jp * 8];
                    mma_f16(acc1[2 * jp],     a[0], a[1], a[2], a[3], b.x, b.y);
                    mma_f16(acc1[2 * jp + 1], a[0], a[1], a[2], a[3], b.z, b.w);
                }
            }
            #pragma unroll
            for (int sl = 0; sl < 4; sl++) {
                int j0 = 2 * sl, j1 = 2 * sl + 1;
                float2 bb0 = *(const float2*)(b1s + 64 * hf + 8 * j0 + 2 * ti);
                float2 bb1 = *(const float2*)(b1s + 64 * hf + 8 * j1 + 2 * ti);
                ha[4 * hf + sl][0] = pack_h2(gelu_fast(acc1[j0][0] + bb0.x),
                                             gelu_fast(acc1[j0][1] + bb0.y));
                ha[4 * hf + sl][1] = pack_h2(gelu_fast(acc1[j0][2] + bb0.x),
                                             gelu_fast(acc1[j0][3] + bb0.y));
                ha[4 * hf + sl][2] = pack_h2(gelu_fast(acc1[j1][0] + bb1.x),
                                             gelu_fast(acc1[j1][1] + bb1.y));
                ha[4 * hf + sl][3] = pack_h2(gelu_fast(acc1[j1][2] + bb1.x),
                                             gelu_fast(acc1[j1][3] + bb1.y));
            }
        }
        __syncwarp();   // A1 fully consumed

        // stage first next-tile pixel
        if (hn) {
            int pix = nxt * 32 + wid * 4;
            stage_pixel(rec_sa, cost + (size_t)pix * (GGRP * DDISP), lid);
        }

        // ---- GEMM2 + epilogue in 4 n-quarters; one gather batch per quarter ----
        #pragma unroll
        for (int q = 0; q < 4; q++) {
            float acc2[4][4];
            #pragma unroll
            for (int j = 0; j < 4; j++)
                #pragma unroll
                for (int u = 0; u < 4; u++) acc2[j][u] = 0.f;
            #pragma unroll
            for (int s = 0; s < 8; s++) {
                const uint4* bq = B2q + s * BQ_S + ti * 66 + (2 * q) * 8 + g;
                uint4 b0 = bq[0], b1v = bq[8];
                mma_f16(acc2[0], ha[s][0], ha[s][1], ha[s][2], ha[s][3], b0.x, b0.y);
                mma_f16(acc2[1], ha[s][0], ha[s][1], ha[s][2], ha[s][3], b0.z, b0.w);
                mma_f16(acc2[2], ha[s][0], ha[s][1], ha[s][2], ha[s][3], b1v.x, b1v.y);
                mma_f16(acc2[3], ha[s][0], ha[s][1], ha[s][2], ha[s][3], b1v.z, b1v.w);
            }
            #pragma unroll
            for (int s = 0; s < 4; s++) {
                int kb = 16 * s + 2 * ti;
                uint32_t a0 = oh2(d0, kb);
                uint32_t a1 = oh2(d1, kb);
                uint32_t a2 = oh2(d0, kb + 8);
                uint32_t a3 = oh2(d1, kb + 8);
                const uint4* bq = B2q + (8 + s) * BQ_S + ti * 66 + (2 * q) * 8 + g;
                uint4 b0 = bq[0], b1v = bq[8];
                mma_f16(acc2[0], a0, a1, a2, a3, b0.x, b0.y);
                mma_f16(acc2[1], a0, a1, a2, a3, b0.z, b0.w);
                mma_f16(acc2[2], a0, a1, a2, a3, b1v.x, b1v.y);
                mma_f16(acc2[3], a0, a1, a2, a3, b1v.z, b1v.w);
            }
            // epilogue for this quarter
            {
                float* o0 = out_embed + (size_t)(m0 + mbase + g) * EDIM + 32 * q + 2 * ti;
                float* o1 = out_embed + (size_t)(m0 + mbase + g + 8) * EDIM + 32 * q + 2 * ti;
                #pragma unroll
                for (int jj = 0; jj < 4; jj++) {
                    *(float2*)(o0 + 8 * jj) = make_float2(acc2[jj][0], acc2[jj][1]);
                    *(float2*)(o1 + 8 * jj) = make_float2(acc2[jj][2], acc2[jj][3]);
                }
            }
            // land batch q, extract, stage batch q+1
            if (hn) {
                CP_WAIT0();
                __syncwarp();
                extract_batch(recw, A1h, q, drawn[q], lid);
                if ((lid & 7) == 0 && out_label)
                    out_label[nxt * TILE_M + mbase + 4 * q + lrow] = (float)drawn[q];
                __syncwarp();
                if (q < 3) {
                    int pix = nxt * 32 + wid * 4 + q + 1;
                    stage_pixel(rec_sa, cost + (size_t)pix * (GGRP * DDISP), lid);
                }
            }
        }
        __syncwarp();
    }
}

// ---------------- launch ----------------
extern "C" void kernel_launch(void* const* d_in, const int* in_sizes, int n_in,
                              void* d_out, int out_size) {
    const float* cost  = (const float*)d_in[0];
    const int*   label = (const int*)d_in[1];
    // d_in[2] = context (unused: layers=[] passthrough)
    const float* W1 = (const float*)d_in[3];
    const float* b1 = (const float*)d_in[4];
    const float* W2 = (const float*)d_in[5];
    const float* b2 = (const float*)d_in[6];
    const float* Wp = (const float*)d_in[7];

    float* out = (float*)d_out;
    float* out_label = (out_size >= TOT_ELEMS) ? (out + EMB_ELEMS) : nullptr;

    cudaFuncSetAttribute(propagation_kernel,
                         cudaFuncAttributeMaxDynamicSharedMemorySize, SMEM_TOTAL);

    propagation_kernel<<<GRID_X, NTHR, SMEM_TOTAL>>>(cost, label, W1, b1, W2, b2, Wp,
                                                     out, out_label);
}